// round 7
// baseline (speedup 1.0000x reference)
#include <cuda_runtime.h>
#include <cstdint>

#define HW 65536
#define NPIX 131072   // B * H * W = 2*256*256
#define OUT_PRIOR 393216
#define OUT_Y 1310720

typedef unsigned long long ull;

__device__ __forceinline__ ull pack2(float lo, float hi) {
    ull r; asm("mov.b64 %0, {%1, %2};" : "=l"(r) : "f"(lo), "f"(hi)); return r;
}
__device__ __forceinline__ void unpack2(ull v, float& lo, float& hi) {
    asm("mov.b64 {%0, %1}, %2;" : "=f"(lo), "=f"(hi) : "l"(v));
}
__device__ __forceinline__ void ffma2(ull& d, ull a, ull b) {
    asm("fma.rn.f32x2 %0, %1, %2, %0;" : "+l"(d) : "l"(a), "l"(b));
}
__device__ __forceinline__ ull addf2(ull a, ull b) {
    ull r; asm("add.rn.f32x2 %0, %1, %2;" : "=l"(r) : "l"(a), "l"(b)); return r;
}
__device__ __forceinline__ void cp_async4(uint32_t dst, const void* src, int sz) {
    asm volatile("cp.async.ca.shared.global [%0], [%1], 4, %2;" :: "r"(dst), "l"(src), "r"(sz));
}
__device__ __forceinline__ void cp_commit() { asm volatile("cp.async.commit_group;"); }
__device__ __forceinline__ void cp_wait0()  { asm volatile("cp.async.wait_group 0;" ::: "memory"); }
__device__ __forceinline__ uint32_t smem_u32(const void* p) {
    uint32_t a;
    asm("{ .reg .u64 t; cvta.to.shared.u64 t, %1; cvt.u32.u64 %0, t; }" : "=r"(a) : "l"(p));
    return a;
}

// ---------------- device scratch (static: no allocs allowed) ----------------
__device__ float g_h1[2u*32u*7u*HW];
__device__ float g_h2[2u*32u*7u*HW];
__device__ float g_guide[2u*7u*HW];
__device__ float g_domk[4*27];
__device__ float g_wt[4u*NPIX*27u];
__device__ float g_xc[2u*3u*HW];
__device__ float g_ypre[NPIX];
__device__ float g_r[NPIX];

// ---------------- init: xc = x[:, :, 2:5] (raw, no relu) ----------------
__global__ void init_xc_kernel(const float* __restrict__ x) {
    int t = blockIdx.x * 256 + threadIdx.x;
    int b = t / (3 * HW);
    int rem = t - b * 3 * HW;
    int s = rem / HW;
    int hw = rem - s * HW;
    g_xc[t] = x[(b * 7 + 2 + s) * HW + hw];
}

// ---------------- conv1: 1 -> 32, 3x3x3 SAME, relu ----------------
__global__ __launch_bounds__(256) void conv1_kernel(
    const float* __restrict__ x, const float* __restrict__ w, const float* __restrict__ bias)
{
    __shared__ float ws[27 * 32];   // [tap][oc]
    __shared__ float bs[32];
    int tid = threadIdx.x;
    for (int t = tid; t < 864; t += 256) {
        int tap = t >> 5, oc = t & 31;
        ws[t] = w[oc * 27 + tap];
    }
    if (tid < 32) bs[tid] = bias[tid];
    __syncthreads();

    int hw = blockIdx.x * 256 + tid;
    int h = hw >> 8, wq = hw & 255;
    int d = blockIdx.y, b = blockIdx.z;

    const float* xp = x + (size_t)(b * 7 + d) * HW + hw;
    bool h0 = h > 0, h2 = h < 255, w0 = wq > 0, w2 = wq < 255;

    float v[27];
#pragma unroll
    for (int kd = 0; kd < 3; ++kd) {
        int dd = d + kd - 1;
        bool dok = (unsigned)dd < 7u;
        const float* ipd = xp + (kd - 1) * HW;
#pragma unroll
        for (int kh = 0; kh < 3; ++kh) {
            bool hok = (kh == 0) ? h0 : (kh == 2 ? h2 : true);
            const float* iph = ipd + (kh - 1) * 256;
#pragma unroll
            for (int kw = 0; kw < 3; ++kw) {
                bool wok = (kw == 0) ? w0 : (kw == 2 ? w2 : true);
                v[kd * 9 + kh * 3 + kw] = (dok && hok && wok) ? iph[kw - 1] : 0.f;
            }
        }
    }

    float acc[32];
#pragma unroll
    for (int oc = 0; oc < 32; ++oc) acc[oc] = bs[oc];

    const float4* wp = (const float4*)ws;
#pragma unroll
    for (int tap = 0; tap < 27; ++tap) {
        float xv = v[tap];
#pragma unroll
        for (int q = 0; q < 8; ++q) {
            float4 ww = wp[tap * 8 + q];
            acc[q * 4 + 0] += xv * ww.x;
            acc[q * 4 + 1] += xv * ww.y;
            acc[q * 4 + 2] += xv * ww.z;
            acc[q * 4 + 3] += xv * ww.w;
        }
    }

    float* ob = g_h1 + (size_t)b * 32 * 7 * HW + (size_t)d * HW + hw;
#pragma unroll
    for (int oc = 0; oc < 32; ++oc)
        ob[(size_t)oc * 7 * HW] = fmaxf(acc[oc], 0.f);
}

// ---------------- conv32 v5: f32x2 w-pairs, dup weights, cp.async, 32x64 tile ----
// dir == 0 : g_h1 -> g_h2 ; dir == 1 : g_h2 -> g_h1
// grid: (32 tiles [4w x 8h], 7 d, b*4 + ocg)
// thread (th=tid>>5, tw=tid&31): pixel pairs at cols (tx+2tw, tx+2tw+1),
// rows ty+th, ty+th+8, ty+th+16, ty+th+24  -> 4 ull pairs x 8 oc accumulators.
#define T5ROW 66
#define T5SLICE 2244           // 34*66
#define T5ELEMS 6732           // 3*2244
#define CONV5_SMEM (55296 + 64 + 2 * T5ELEMS * 4)   // 109,216 B
__global__ __launch_bounds__(256, 2) void conv32_v5(
    int dir, const float* __restrict__ w, const float* __restrict__ bias)
{
    extern __shared__ char smemraw[];
    ull*   ws2 = (ull*)smemraw;                 // 6912 dup-pair weights
    ull*   bs2 = (ull*)(smemraw + 55296);       // 8
    float* tls = (float*)(smemraw + 55360);     // 2 * 6732
    uint32_t tls_u = smem_u32(tls);

    int tid = threadIdx.x;
    int zb = blockIdx.z;
    int b = zb >> 2, ocg = zb & 3;

    for (int t = tid; t < 6912; t += 256) {
        int o = t & 7;
        int rest = t >> 3;                      // = ic*27 + tap
        int ic = rest / 27, tap = rest - ic * 27;
        float wv = w[((ocg * 8 + o) * 32 + ic) * 27 + tap];
        ws2[t] = pack2(wv, wv);
    }
    if (tid < 8) { float bv = bias[ocg * 8 + tid]; bs2[tid] = pack2(bv, bv); }

    int tile = blockIdx.x;                      // 0..31
    int tx = (tile & 3) << 6;
    int ty = (tile >> 2) << 5;
    int d = blockIdx.y;
    int tw = tid & 31, th = tid >> 5;

    const float* in = dir ? g_h2 : g_h1;
    float* out = dir ? g_h1 : g_h2;
    const float* inb = in + (size_t)b * 32 * 7 * HW;

    // loader mapping: 102 rows (3 d-slices x 34), 2 half-rows of 33 per row
    int lrow = tid >> 1, lhalf = tid & 1;
    int ldd = 0, lr = lrow;
    if (lr >= 68) { ldd = 2; lr -= 68; } else if (lr >= 34) { ldd = 1; lr -= 34; }
    int gd_l = d + ldd - 1;
    int gh_l = ty + lr - 1;
    bool rowok = (lrow < 102) && ((unsigned)gd_l < 7u) && ((unsigned)gh_l < 256u);
    int rowoff = (lrow < 102) ? (ldd * T5SLICE + lr * T5ROW + lhalf * 33) : 0;
    size_t srcrow = rowok ? ((size_t)gd_l * HW + (size_t)gh_l * 256) : 0;

#define LOAD_TILE5(icv, buf)                                                   \
    {                                                                          \
        const float* icb = inb + (size_t)(icv) * 7 * HW;                       \
        if (lrow < 102) {                                                      \
            uint32_t dbase = tls_u + (uint32_t)((buf) * T5ELEMS + rowoff) * 4; \
            const float* s0 = icb + srcrow;                                    \
            _Pragma("unroll")                                                  \
            for (int j = 0; j < 33; ++j) {                                     \
                int gw = tx + lhalf * 33 + j - 1;                              \
                bool ok = rowok && ((unsigned)gw < 256u);                      \
                const float* src = ok ? (s0 + gw) : icb;                       \
                cp_async4(dbase + j * 4, src, ok ? 4 : 0);                     \
            }                                                                  \
        }                                                                      \
        cp_commit();                                                           \
    }

    LOAD_TILE5(0, 0);

    ull a0[8], a1[8], a2[8], a3[8];
#pragma unroll
    for (int o = 0; o < 8; ++o) { a0[o] = 0; a1[o] = 0; a2[o] = 0; a3[o] = 0; }

    cp_wait0();
    __syncthreads();   // weights + first tile ready

    for (int ic = 0; ic < 32; ++ic) {
        const float* cur = tls + (ic & 1) * T5ELEMS;
        if (ic < 31) LOAD_TILE5(ic + 1, (ic + 1) & 1);

        const ull* wp = ws2 + ic * 216;
#pragma unroll
        for (int kd = 0; kd < 3; ++kd) {
#pragma unroll
            for (int kh = 0; kh < 3; ++kh) {
                const float* rb = cur + kd * T5SLICE + (th + kh) * T5ROW + 2 * tw;
                ull uA0 = *(const ull*)rb;
                ull uB0 = *(const ull*)(rb + 2);
                ull uA1 = *(const ull*)(rb + 8 * T5ROW);
                ull uB1 = *(const ull*)(rb + 8 * T5ROW + 2);
                ull uA2 = *(const ull*)(rb + 16 * T5ROW);
                ull uB2 = *(const ull*)(rb + 16 * T5ROW + 2);
                ull uA3 = *(const ull*)(rb + 24 * T5ROW);
                ull uB3 = *(const ull*)(rb + 24 * T5ROW + 2);
                float e0, e1, f0, f1;
                unpack2(uA0, e0, e1); unpack2(uB0, f0, f1); ull m0 = pack2(e1, f0);
                unpack2(uA1, e0, e1); unpack2(uB1, f0, f1); ull m1 = pack2(e1, f0);
                unpack2(uA2, e0, e1); unpack2(uB2, f0, f1); ull m2 = pack2(e1, f0);
                unpack2(uA3, e0, e1); unpack2(uB3, f0, f1); ull m3 = pack2(e1, f0);
                const ull* wt3 = wp + (kd * 9 + kh * 3) * 8;
                // kw = 0
                {
                    const ulonglong2* w4 = (const ulonglong2*)wt3;
#pragma unroll
                    for (int q = 0; q < 4; ++q) {
                        ulonglong2 wv = w4[q];
                        ffma2(a0[q*2+0], uA0, wv.x); ffma2(a1[q*2+0], uA1, wv.x);
                        ffma2(a2[q*2+0], uA2, wv.x); ffma2(a3[q*2+0], uA3, wv.x);
                        ffma2(a0[q*2+1], uA0, wv.y); ffma2(a1[q*2+1], uA1, wv.y);
                        ffma2(a2[q*2+1], uA2, wv.y); ffma2(a3[q*2+1], uA3, wv.y);
                    }
                }
                // kw = 1
                {
                    const ulonglong2* w4 = (const ulonglong2*)(wt3 + 8);
#pragma unroll
                    for (int q = 0; q < 4; ++q) {
                        ulonglong2 wv = w4[q];
                        ffma2(a0[q*2+0], m0, wv.x); ffma2(a1[q*2+0], m1, wv.x);
                        ffma2(a2[q*2+0], m2, wv.x); ffma2(a3[q*2+0], m3, wv.x);
                        ffma2(a0[q*2+1], m0, wv.y); ffma2(a1[q*2+1], m1, wv.y);
                        ffma2(a2[q*2+1], m2, wv.y); ffma2(a3[q*2+1], m3, wv.y);
                    }
                }
                // kw = 2
                {
                    const ulonglong2* w4 = (const ulonglong2*)(wt3 + 16);
#pragma unroll
                    for (int q = 0; q < 4; ++q) {
                        ulonglong2 wv = w4[q];
                        ffma2(a0[q*2+0], uB0, wv.x); ffma2(a1[q*2+0], uB1, wv.x);
                        ffma2(a2[q*2+0], uB2, wv.x); ffma2(a3[q*2+0], uB3, wv.x);
                        ffma2(a0[q*2+1], uB0, wv.y); ffma2(a1[q*2+1], uB1, wv.y);
                        ffma2(a2[q*2+1], uB2, wv.y); ffma2(a3[q*2+1], uB3, wv.y);
                    }
                }
            }
        }

        if (ic < 31) { cp_wait0(); __syncthreads(); }
    }

    size_t ob = (size_t)b * 32 * 7 * HW + (size_t)d * HW + (size_t)(ty + th) * 256 + tx + 2 * tw;
#pragma unroll
    for (int o = 0; o < 8; ++o) {
        size_t pp = ob + (size_t)(ocg * 8 + o) * 7 * HW;
        float lo, hi;
        unpack2(addf2(a0[o], bs2[o]), lo, hi);
        *(ull*)(out + pp) = pack2(fmaxf(lo, 0.f), fmaxf(hi, 0.f));
        unpack2(addf2(a1[o], bs2[o]), lo, hi);
        *(ull*)(out + pp + 8 * 256) = pack2(fmaxf(lo, 0.f), fmaxf(hi, 0.f));
        unpack2(addf2(a2[o], bs2[o]), lo, hi);
        *(ull*)(out + pp + 16 * 256) = pack2(fmaxf(lo, 0.f), fmaxf(hi, 0.f));
        unpack2(addf2(a3[o], bs2[o]), lo, hi);
        *(ull*)(out + pp + 24 * 256) = pack2(fmaxf(lo, 0.f), fmaxf(hi, 0.f));
    }
}

// ---------------- conv4 v3: 32 -> 1 SAME + x, f32x2 w-pairs, 16x64 tile ----
#define T6ROW 66
#define T6SLICE 1188           // 18*66
#define T6ELEMS 3564
__global__ __launch_bounds__(256) void conv4_v3(
    const float* __restrict__ x, const float* __restrict__ w,
    const float* __restrict__ bias, float* __restrict__ out_prior)
{
    __shared__ ull wd[864];                 // dup-pair weights [ic*27+tap]
    __shared__ float tls[2 * T6ELEMS];
    uint32_t tls_u = smem_u32(tls);

    int tid = threadIdx.x;
    for (int t = tid; t < 864; t += 256) { float wv = w[t]; wd[t] = pack2(wv, wv); }

    int tile = blockIdx.x;                  // 0..63 : 4w x 16h
    int tx = (tile & 3) << 6;
    int ty = (tile >> 2) << 4;
    int d = blockIdx.y, b = blockIdx.z;
    int tw = tid & 31, th = tid >> 5;

    const float* inb = g_h1 + (size_t)b * 32 * 7 * HW;

    // loader: 54 rows (3 x 18), 2 half-rows of 33
    int lrow = tid >> 1, lhalf = tid & 1;
    int ldd = 0, lr = lrow;
    if (lr >= 36) { ldd = 2; lr -= 36; } else if (lr >= 18) { ldd = 1; lr -= 18; }
    int gd_l = d + ldd - 1;
    int gh_l = ty + lr - 1;
    bool rowok = (lrow < 54) && ((unsigned)gd_l < 7u) && ((unsigned)gh_l < 256u);
    int rowoff = (lrow < 54) ? (ldd * T6SLICE + lr * T6ROW + lhalf * 33) : 0;
    size_t srcrow = rowok ? ((size_t)gd_l * HW + (size_t)gh_l * 256) : 0;

#define LOAD_TILE6(icv, buf)                                                   \
    {                                                                          \
        const float* icb = inb + (size_t)(icv) * 7 * HW;                       \
        if (lrow < 54) {                                                       \
            uint32_t dbase = tls_u + (uint32_t)((buf) * T6ELEMS + rowoff) * 4; \
            const float* s0 = icb + srcrow;                                    \
            _Pragma("unroll")                                                  \
            for (int j = 0; j < 33; ++j) {                                     \
                int gw = tx + lhalf * 33 + j - 1;                              \
                bool ok = rowok && ((unsigned)gw < 256u);                      \
                const float* src = ok ? (s0 + gw) : icb;                       \
                cp_async4(dbase + j * 4, src, ok ? 4 : 0);                     \
            }                                                                  \
        }                                                                      \
        cp_commit();                                                           \
    }

    LOAD_TILE6(0, 0);
    ull acc0 = 0, acc1 = 0;
    cp_wait0();
    __syncthreads();

    for (int ic = 0; ic < 32; ++ic) {
        const float* cur = tls + (ic & 1) * T6ELEMS;
        if (ic < 31) LOAD_TILE6(ic + 1, (ic + 1) & 1);

        const ull* wic = wd + ic * 27;
#pragma unroll
        for (int kd = 0; kd < 3; ++kd) {
#pragma unroll
            for (int kh = 0; kh < 3; ++kh) {
                const float* r0 = cur + kd * T6SLICE + (th + kh) * T6ROW + 2 * tw;
                const float* r1 = r0 + 8 * T6ROW;
                ull uA0 = *(const ull*)r0, uB0 = *(const ull*)(r0 + 2);
                ull uA1 = *(const ull*)r1, uB1 = *(const ull*)(r1 + 2);
                float e0, e1, f0, f1;
                unpack2(uA0, e0, e1); unpack2(uB0, f0, f1); ull m0 = pack2(e1, f0);
                unpack2(uA1, e0, e1); unpack2(uB1, f0, f1); ull m1 = pack2(e1, f0);
                ull w0 = wic[kd * 9 + kh * 3 + 0];
                ull w1 = wic[kd * 9 + kh * 3 + 1];
                ull w2 = wic[kd * 9 + kh * 3 + 2];
                ffma2(acc0, uA0, w0); ffma2(acc1, uA1, w0);
                ffma2(acc0, m0,  w1); ffma2(acc1, m1,  w1);
                ffma2(acc0, uB0, w2); ffma2(acc1, uB1, w2);
            }
        }

        if (ic < 31) { cp_wait0(); __syncthreads(); }
    }

    float bv = bias[0];
    ull bb = pack2(bv, bv);
    size_t oi0 = (size_t)(b * 7 + d) * HW + (size_t)(ty + th) * 256 + tx + 2 * tw;
    size_t oi1 = oi0 + 8 * 256;
    ull g0 = addf2(addf2(acc0, bb), *(const ull*)(x + oi0));
    ull g1 = addf2(addf2(acc1, bb), *(const ull*)(x + oi1));
    *(ull*)(g_guide + oi0) = g0;  *(ull*)(g_guide + oi1) = g1;
    *(ull*)(out_prior + oi0) = g0; *(ull*)(out_prior + oi1) = g1;
}

// ---------------- domain kernel ----------------
__global__ void domain_kernel(
    const float* __restrict__ spat,
    const float* __restrict__ dw1, const float* __restrict__ db1,
    const float* __restrict__ dw2, const float* __restrict__ db2)
{
    int i = blockIdx.x;
    int tid = threadIdx.x;
    __shared__ float sp[343], hid[1000], w1s[216], w2s[216];
    for (int t = tid; t < 343; t += 256) sp[t] = spat[t];
    for (int t = tid; t < 216; t += 256) { w1s[t] = dw1[i * 216 + t]; w2s[t] = dw2[i * 216 + t]; }
    __syncthreads();

    for (int idx = tid; idx < 1000; idx += 256) {
        int m = idx / 125, p = idx % 125;
        int z = p / 25, y = (p / 5) % 5, xx = p % 5;
        float a = db1[i * 8 + m];
#pragma unroll
        for (int kd = 0; kd < 3; ++kd)
#pragma unroll
            for (int kh = 0; kh < 3; ++kh)
#pragma unroll
                for (int kw = 0; kw < 3; ++kw)
                    a += sp[(z + kd) * 49 + (y + kh) * 7 + (xx + kw)] * w1s[m * 27 + kd * 9 + kh * 3 + kw];
        hid[idx] = fmaxf(a, 0.f);
    }
    __syncthreads();

    if (tid < 27) {
        int z = tid / 9, y = (tid / 3) % 3, xx = tid % 3;
        float a = db2[i];
#pragma unroll
        for (int m = 0; m < 8; ++m)
#pragma unroll
            for (int kd = 0; kd < 3; ++kd)
#pragma unroll
                for (int kh = 0; kh < 3; ++kh)
#pragma unroll
                    for (int kw = 0; kw < 3; ++kw)
                        a += hid[m * 125 + (z + kd) * 25 + (y + kh) * 5 + (xx + kw)] *
                             w2s[m * 27 + kd * 9 + kh * 3 + kw];
        g_domk[i * 27 + tid] = fmaxf(a, 0.f);
    }
}

// ---------------- range kernel: warp per pixel ----------------
__global__ __launch_bounds__(256) void rangek_kernel(
    const float* __restrict__ rw1, const float* __restrict__ rb1,
    const float* __restrict__ rw2, const float* __restrict__ rb2)
{
    __shared__ float gp8[8][344];
    __shared__ float hid8[8][1008];
    __shared__ float w1s[216];      // [tap*8 + m]
    __shared__ float w2s[216];      // [m*27 + tap]

    int tid = threadIdx.x;
    int wid = tid >> 5, lane = tid & 31;
    int pix = blockIdx.x * 8 + wid;
    int b = pix >> 16;
    int hw = pix & 65535;
    int h = hw >> 8, wq = hw & 255;

    const float* gb = g_guide + (size_t)b * 7 * HW;
    float center = gb[3 * HW + hw];

    for (int idx = lane; idx < 343; idx += 32) {
        int d = idx / 49, rr = idx % 49;
        int ii = rr / 7, jj = rr % 7;
        int hh = h - 3 + ii, ww = wq - 3 + jj;
        float v = 0.f;
        if ((unsigned)hh < 256u && (unsigned)ww < 256u) v = gb[d * HW + hh * 256 + ww];
        gp8[wid][idx] = fabsf(v - center);
    }

    for (int i = 0; i < 4; ++i) {
        __syncthreads();
        for (int t = tid; t < 216; t += 256) {
            int m = t / 27, tap = t % 27;
            w1s[tap * 8 + m] = rw1[i * 216 + t];
            w2s[t] = rw2[i * 216 + t];
        }
        __syncthreads();

        const float* gp = gp8[wid];
#pragma unroll
        for (int rep = 0; rep < 4; ++rep) {
            int p = lane + (rep << 5);
            int pp = p < 125 ? p : 124;
            int z = pp / 25, y = (pp / 5) % 5, xx = pp % 5;
            const float* gpb = gp + z * 49 + y * 7 + xx;
            float acc[8];
#pragma unroll
            for (int m = 0; m < 8; ++m) acc[m] = rb1[i * 8 + m];
#pragma unroll
            for (int kd = 0; kd < 3; ++kd)
#pragma unroll
                for (int kh = 0; kh < 3; ++kh)
#pragma unroll
                    for (int kw = 0; kw < 3; ++kw) {
                        float g = gpb[kd * 49 + kh * 7 + kw];
                        int tap = kd * 9 + kh * 3 + kw;
                        const float4* w4 = (const float4*)(w1s + tap * 8);
                        float4 wa = w4[0], wb = w4[1];
                        acc[0] += g * wa.x; acc[1] += g * wa.y;
                        acc[2] += g * wa.z; acc[3] += g * wa.w;
                        acc[4] += g * wb.x; acc[5] += g * wb.y;
                        acc[6] += g * wb.z; acc[7] += g * wb.w;
                    }
            if (p < 125) {
#pragma unroll
                for (int m = 0; m < 8; ++m)
                    hid8[wid][m * 125 + p] = fmaxf(acc[m], 0.f);
            }
        }
        __syncwarp();

        float wt = 0.f;
        if (lane < 27) {
            int z = lane / 9, y = (lane / 3) % 3, xx = lane % 3;
            float a = rb2[i];
            const float* hd = hid8[wid];
#pragma unroll
            for (int m = 0; m < 8; ++m)
#pragma unroll
                for (int kd = 0; kd < 3; ++kd)
#pragma unroll
                    for (int kh = 0; kh < 3; ++kh)
#pragma unroll
                        for (int kw = 0; kw < 3; ++kw)
                            a += hd[m * 125 + (z + kd) * 25 + (y + kh) * 5 + (xx + kw)] *
                                 w2s[m * 27 + kd * 9 + kh * 3 + kw];
            a = fmaxf(a, 0.f);
            wt = g_domk[i * 27 + lane] * a;
        }
        float s = wt;
#pragma unroll
        for (int off = 16; off; off >>= 1) s += __shfl_down_sync(0xffffffffu, s, off);
        s = __shfl_sync(0xffffffffu, s, 0);
        if (lane < 27)
            g_wt[((size_t)i * NPIX + pix) * 27 + lane] = wt / (s + 1e-6f);
        __syncwarp();
    }
}

// ---------------- bilateral gather per block i ----------------
__global__ void bilateral_kernel(int i, const float* __restrict__ x) {
    int pix = blockIdx.x * 256 + threadIdx.x;
    int b = pix >> 16;
    int hw = pix & 65535;
    int h = hw >> 8, wq = hw & 255;

    const float* wp = g_wt + ((size_t)i * NPIX + pix) * 27;
    const float* xcb = g_xc + (size_t)b * 3 * HW;

    float y = 0.f;
#pragma unroll
    for (int dz = 0; dz < 3; ++dz) {
#pragma unroll
        for (int dy = 0; dy < 3; ++dy) {
            int hh = h + dy - 1;
            bool hok = (unsigned)hh < 256u;
#pragma unroll
            for (int dx = 0; dx < 3; ++dx) {
                int ww = wq + dx - 1;
                bool wok = (unsigned)ww < 256u;
                float v = (hok && wok) ? xcb[dz * HW + hh * 256 + ww] : 0.f;
                y += wp[dz * 9 + dy * 3 + dx] * v;
            }
        }
    }
    y = fmaxf(y, 0.f);
    float ref = x[(b * 7 + 3) * HW + hw];
    g_ypre[pix] = y;
    g_r[pix] = y - ref;
}

// ---------------- alfa residual kernel per block i ----------------
__global__ void alfa_kernel(int i, const float* __restrict__ x,
                            const float* __restrict__ aw, const float* __restrict__ ab,
                            float* __restrict__ out)
{
    int pix = blockIdx.x * 256 + threadIdx.x;
    int b = pix >> 16;
    int hw = pix & 65535;
    int h = hw >> 8, wq = hw & 255;

    const float* awp = aw + i * 9;
    const float* rb = g_r + (size_t)b * HW;
    float alfa = ab[i];
#pragma unroll
    for (int ky = 0; ky < 3; ++ky) {
        int hh = h + ky - 1;
        if ((unsigned)hh >= 256u) continue;
#pragma unroll
        for (int kx = 0; kx < 3; ++kx) {
            int ww = wq + kx - 1;
            if ((unsigned)ww >= 256u) continue;
            alfa += awp[ky * 3 + kx] * rb[hh * 256 + ww];
        }
    }
    float rc = g_r[pix];
    float y = fmaxf(g_ypre[pix] + alfa * rc, 0.f);

    out[OUT_Y + (size_t)i * NPIX + pix] = y;
    g_xc[(b * 3 + 1) * HW + hw] = y;
    if (i == 0) {
        g_xc[(b * 3 + 0) * HW + hw] = fmaxf(x[(b * 7 + 2) * HW + hw], 0.f);
        g_xc[(b * 3 + 2) * HW + hw] = fmaxf(x[(b * 7 + 4) * HW + hw], 0.f);
    }
    if (i == 3) {
        out[(b * 3 + 0) * HW + hw] = g_xc[(b * 3 + 0) * HW + hw];
        out[(b * 3 + 1) * HW + hw] = y;
        out[(b * 3 + 2) * HW + hw] = g_xc[(b * 3 + 2) * HW + hw];
    }
}

// ---------------- launch ----------------
extern "C" void kernel_launch(void* const* d_in, const int* in_sizes, int n_in,
                              void* d_out, int out_size)
{
    const float* x    = (const float*)d_in[0];
    const float* spat = (const float*)d_in[1];
    const float* pw1  = (const float*)d_in[2];
    const float* pb1  = (const float*)d_in[3];
    const float* pw2  = (const float*)d_in[4];
    const float* pb2  = (const float*)d_in[5];
    const float* pw3  = (const float*)d_in[6];
    const float* pb3  = (const float*)d_in[7];
    const float* pw4  = (const float*)d_in[8];
    const float* pb4  = (const float*)d_in[9];
    const float* dw1  = (const float*)d_in[10];
    const float* db1  = (const float*)d_in[11];
    const float* dw2  = (const float*)d_in[12];
    const float* db2  = (const float*)d_in[13];
    const float* rw1  = (const float*)d_in[14];
    const float* rb1  = (const float*)d_in[15];
    const float* rw2  = (const float*)d_in[16];
    const float* rb2  = (const float*)d_in[17];
    const float* aw   = (const float*)d_in[18];
    const float* ab   = (const float*)d_in[19];
    float* out = (float*)d_out;

    cudaFuncSetAttribute(conv32_v5, cudaFuncAttributeMaxDynamicSharedMemorySize, CONV5_SMEM);

    init_xc_kernel<<<1536, 256>>>(x);
    conv1_kernel<<<dim3(256, 7, 2), 256>>>(x, pw1, pb1);
    conv32_v5<<<dim3(32, 7, 8), 256, CONV5_SMEM>>>(0, pw2, pb2);   // h1 -> h2
    conv32_v5<<<dim3(32, 7, 8), 256, CONV5_SMEM>>>(1, pw3, pb3);   // h2 -> h1
    conv4_v3<<<dim3(64, 7, 2), 256>>>(x, pw4, pb4, out + OUT_PRIOR);
    domain_kernel<<<4, 256>>>(spat, dw1, db1, dw2, db2);
    rangek_kernel<<<NPIX / 8, 256>>>(rw1, rb1, rw2, rb2);

    for (int i = 0; i < 4; ++i) {
        bilateral_kernel<<<NPIX / 256, 256>>>(i, x);
        alfa_kernel<<<NPIX / 256, 256>>>(i, x, aw, ab, out);
    }
}

// round 8
// speedup vs baseline: 1.2191x; 1.2191x over previous
#include <cuda_runtime.h>
#include <cstdint>

#define HW 65536
#define NPIX 131072   // B * H * W = 2*256*256
#define OUT_PRIOR 393216
#define OUT_Y 1310720

typedef unsigned long long ull;

__device__ __forceinline__ ull pack2(float lo, float hi) {
    ull r; asm("mov.b64 %0, {%1, %2};" : "=l"(r) : "f"(lo), "f"(hi)); return r;
}
__device__ __forceinline__ void unpack2(ull v, float& lo, float& hi) {
    asm("mov.b64 {%0, %1}, %2;" : "=f"(lo), "=f"(hi) : "l"(v));
}
__device__ __forceinline__ void ffma2(ull& d, ull a, ull b) {
    asm("fma.rn.f32x2 %0, %1, %2, %0;" : "+l"(d) : "l"(a), "l"(b));
}
__device__ __forceinline__ ull addf2(ull a, ull b) {
    ull r; asm("add.rn.f32x2 %0, %1, %2;" : "=l"(r) : "l"(a), "l"(b)); return r;
}

// ---------------- device scratch (static: no allocs allowed) ----------------
__device__ float g_h1[2u*32u*7u*HW];
__device__ float g_h2[2u*32u*7u*HW];
__device__ float g_guide[2u*7u*HW];
__device__ float g_domk[4*27];
__device__ float g_wt[4u*NPIX*27u];
__device__ float g_xc[2u*3u*HW];
__device__ float g_ypre[NPIX];
__device__ float g_r[NPIX];

// ---------------- init: xc = x[:, :, 2:5] (raw, no relu) ----------------
__global__ void init_xc_kernel(const float* __restrict__ x) {
    int t = blockIdx.x * 256 + threadIdx.x;           // 0 .. 393215
    int b = t / (3 * HW);
    int rem = t - b * 3 * HW;
    int s = rem / HW;
    int hw = rem - s * HW;
    g_xc[t] = x[(b * 7 + 2 + s) * HW + hw];
}

// ---------------- conv1: 1 -> 32, 3x3x3 SAME, relu ----------------
__global__ __launch_bounds__(256) void conv1_kernel(
    const float* __restrict__ x, const float* __restrict__ w, const float* __restrict__ bias)
{
    __shared__ float ws[27 * 32];   // [tap][oc]
    __shared__ float bs[32];
    int tid = threadIdx.x;
    for (int t = tid; t < 864; t += 256) {
        int tap = t >> 5, oc = t & 31;
        ws[t] = w[oc * 27 + tap];
    }
    if (tid < 32) bs[tid] = bias[tid];
    __syncthreads();

    int hw = blockIdx.x * 256 + tid;
    int h = hw >> 8, wq = hw & 255;
    int d = blockIdx.y, b = blockIdx.z;

    const float* xp = x + (size_t)(b * 7 + d) * HW + hw;
    bool h0 = h > 0, h2 = h < 255, w0 = wq > 0, w2 = wq < 255;

    float v[27];
#pragma unroll
    for (int kd = 0; kd < 3; ++kd) {
        int dd = d + kd - 1;
        bool dok = (unsigned)dd < 7u;
        const float* ipd = xp + (kd - 1) * HW;
#pragma unroll
        for (int kh = 0; kh < 3; ++kh) {
            bool hok = (kh == 0) ? h0 : (kh == 2 ? h2 : true);
            const float* iph = ipd + (kh - 1) * 256;
#pragma unroll
            for (int kw = 0; kw < 3; ++kw) {
                bool wok = (kw == 0) ? w0 : (kw == 2 ? w2 : true);
                v[kd * 9 + kh * 3 + kw] = (dok && hok && wok) ? iph[kw - 1] : 0.f;
            }
        }
    }

    float acc[32];
#pragma unroll
    for (int oc = 0; oc < 32; ++oc) acc[oc] = bs[oc];

    const float4* wp = (const float4*)ws;
#pragma unroll
    for (int tap = 0; tap < 27; ++tap) {
        float xv = v[tap];
#pragma unroll
        for (int q = 0; q < 8; ++q) {
            float4 ww = wp[tap * 8 + q];
            acc[q * 4 + 0] += xv * ww.x;
            acc[q * 4 + 1] += xv * ww.y;
            acc[q * 4 + 2] += xv * ww.z;
            acc[q * 4 + 3] += xv * ww.w;
        }
    }

    float* ob = g_h1 + (size_t)b * 32 * 7 * HW + (size_t)d * HW + hw;
#pragma unroll
    for (int oc = 0; oc < 32; ++oc)
        ob[(size_t)oc * 7 * HW] = fmaxf(acc[oc], 0.f);
}

// ---------------- conv32 v6: f32x2, dup weights in smem, 8 oc/block, 4 px/thread ----
// dir == 0 : g_h1 -> g_h2 ; dir == 1 : g_h2 -> g_h1
// grid: (64 tiles, 7 d, b*4 + ocg); tile 16h x 64w
// thread (th = tid>>5 in 0..7, tw = tid&31) computes pixels:
//   rows ty+th, ty+th+8;  cols tx+tw, tx+tw+32
#define T4ROW 66
#define T4SLICE 1188           // 18*66
#define T4ELEMS 3564           // 3*18*66
#define CONV6SM (55296 + 64 + 2 * T4ELEMS * 4)   // 83,872 B
__global__ __launch_bounds__(256, 2) void conv32_v6(
    int dir, const float* __restrict__ w, const float* __restrict__ bias)
{
    extern __shared__ char smemraw[];
    ull*   ws2 = (ull*)smemraw;                 // 6912 ull dup pairs [(ic*27+tap)*8 + o]
    ull*   bs2 = (ull*)(smemraw + 55296);       // 8 ull
    float* tls = (float*)(smemraw + 55360);     // 2 * 3564 floats

    int tid = threadIdx.x;
    int zb = blockIdx.z;
    int b = zb >> 2, ocg = zb & 3;

    for (int t = tid; t < 6912; t += 256) {
        int o = t & 7;
        int rest = t >> 3;                      // = ic*27 + tap
        int ic = rest / 27, tap = rest - ic * 27;
        float wv = w[((ocg * 8 + o) * 32 + ic) * 27 + tap];
        ws2[t] = pack2(wv, wv);
    }
    if (tid < 8) { float bv = bias[ocg * 8 + tid]; bs2[tid] = pack2(bv, bv); }

    int tile = blockIdx.x;                      // 0..63
    int tx = (tile & 3) << 6;                   // w origin (0,64,128,192)
    int ty = (tile >> 2) << 4;                  // h origin (0..240)
    int d = blockIdx.y;
    int tw = tid & 31, th = tid >> 5;

    const float* in = dir ? g_h2 : g_h1;
    float* out = dir ? g_h1 : g_h2;
    const float* inb = in + (size_t)b * 32 * 7 * HW;

    // preload ic = 0 into buffer 0
    {
        const float* ip = inb;
#pragma unroll
        for (int k = 0; k < 14; ++k) {
            int idx = tid + (k << 8);
            if (idx < T4ELEMS) {
                int dd = (idx >= T4SLICE) + (idx >= 2 * T4SLICE);
                int r  = idx - dd * T4SLICE;
                int hh = r / T4ROW;
                int ww = r - hh * T4ROW;
                int gd = d + dd - 1, gh = ty + hh - 1, gw = tx + ww - 1;
                float v = 0.f;
                if ((unsigned)gd < 7u && (unsigned)gh < 256u && (unsigned)gw < 256u)
                    v = ip[(size_t)gd * HW + gh * 256 + gw];
                tls[idx] = v;
            }
        }
    }

    ull a[16];   // a[o] col-group 0, a[8+o] col-group 1
#pragma unroll
    for (int o = 0; o < 16; ++o) a[o] = 0ull;

    __syncthreads();   // weights + first tile ready

    for (int ic = 0; ic < 32; ++ic) {
        const float* cur = tls + (ic & 1) * T4ELEMS;

        // stage next input tile in registers (hidden behind compute)
        float stage[14];
        if (ic < 31) {
            const float* ip = inb + (size_t)(ic + 1) * 7 * HW;
#pragma unroll
            for (int k = 0; k < 14; ++k) {
                int idx = tid + (k << 8);
                float v = 0.f;
                if (idx < T4ELEMS) {
                    int dd = (idx >= T4SLICE) + (idx >= 2 * T4SLICE);
                    int r  = idx - dd * T4SLICE;
                    int hh = r / T4ROW;
                    int ww = r - hh * T4ROW;
                    int gd = d + dd - 1, gh = ty + hh - 1, gw = tx + ww - 1;
                    if ((unsigned)gd < 7u && (unsigned)gh < 256u && (unsigned)gw < 256u)
                        v = ip[(size_t)gd * HW + gh * 256 + gw];
                }
                stage[k] = v;
            }
        }

        const ull* wp = ws2 + ic * 216;       // 27 taps * 8 dup-pair weights
#pragma unroll
        for (int kd = 0; kd < 3; ++kd) {
#pragma unroll
            for (int kh = 0; kh < 3; ++kh) {
                const float* r0 = cur + kd * T4SLICE + (th + kh) * T4ROW + tw;
                const float* r1 = r0 + 8 * T4ROW;
#pragma unroll
                for (int kw = 0; kw < 3; ++kw) {
                    ull p0 = pack2(r0[kw],      r1[kw]);
                    ull p1 = pack2(r0[kw + 32], r1[kw + 32]);
                    const ulonglong2* w4 = (const ulonglong2*)(wp + ((kd * 9 + kh * 3 + kw) << 3));
#pragma unroll
                    for (int q = 0; q < 4; ++q) {
                        ulonglong2 wv = w4[q];
                        ffma2(a[q * 2 + 0], p0, wv.x);  ffma2(a[8 + q * 2 + 0], p1, wv.x);
                        ffma2(a[q * 2 + 1], p0, wv.y);  ffma2(a[8 + q * 2 + 1], p1, wv.y);
                    }
                }
            }
        }

        if (ic < 31) {
            float* nxt = tls + ((ic + 1) & 1) * T4ELEMS;
#pragma unroll
            for (int k = 0; k < 14; ++k) {
                int idx = tid + (k << 8);
                if (idx < T4ELEMS) nxt[idx] = stage[k];
            }
            __syncthreads();
        }
    }

    size_t ob = (size_t)b * 32 * 7 * HW + (size_t)d * HW + (size_t)(ty + th) * 256 + tx + tw;
#pragma unroll
    for (int o = 0; o < 8; ++o) {
        size_t pp = ob + (size_t)(ocg * 8 + o) * 7 * HW;
        float lo, hi;
        unpack2(addf2(a[o], bs2[o]), lo, hi);
        out[pp] = fmaxf(lo, 0.f);
        out[pp + 8 * 256] = fmaxf(hi, 0.f);
        unpack2(addf2(a[8 + o], bs2[o]), lo, hi);
        out[pp + 32] = fmaxf(lo, 0.f);
        out[pp + 8 * 256 + 32] = fmaxf(hi, 0.f);
    }
}

// ---------------- conv4 v2: 32 -> 1 SAME + x, smem-tiled ----------------
#define TILE_ROW 34
#define TILE_SLICE 612
#define TILE_ELEMS 1836
__global__ __launch_bounds__(256) void conv4_v2(
    const float* __restrict__ x, const float* __restrict__ w,
    const float* __restrict__ bias, float* __restrict__ out_prior)
{
    __shared__ float ws[864];          // [ic*27+tap]
    __shared__ float tls[TILE_ELEMS];
    int tid = threadIdx.x;
    for (int t = tid; t < 864; t += 256) ws[t] = w[t];

    int tileId = blockIdx.x;
    int tx = (tileId & 7) << 5;
    int ty = (tileId >> 3) << 4;
    int d = blockIdx.y, b = blockIdx.z;
    int tw = tid & 31, th = tid >> 5;

    const float* inb = g_h1 + (size_t)b * 32 * 7 * HW;

    float a0 = 0.f, a1 = 0.f;
    for (int ic = 0; ic < 32; ++ic) {
        __syncthreads();
        const float* ip = inb + (size_t)ic * 7 * HW;
#pragma unroll
        for (int k = 0; k < 8; ++k) {
            int idx = tid + (k << 8);
            if (idx < TILE_ELEMS) {
                int dd = idx / TILE_SLICE;
                int r  = idx - dd * TILE_SLICE;
                int hh = r / TILE_ROW;
                int ww = r - hh * TILE_ROW;
                int gd = d + dd - 1;
                int gh = ty + hh - 1;
                int gw = tx + ww - 1;
                float v = 0.f;
                if ((unsigned)gd < 7u && (unsigned)gh < 256u && (unsigned)gw < 256u)
                    v = ip[(size_t)gd * HW + gh * 256 + gw];
                tls[idx] = v;
            }
        }
        __syncthreads();

        const float* wp = ws + ic * 27;
#pragma unroll
        for (int kd = 0; kd < 3; ++kd) {
#pragma unroll
            for (int kh = 0; kh < 3; ++kh) {
                const float* trow = tls + kd * TILE_SLICE + (th + kh) * TILE_ROW + tw;
#pragma unroll
                for (int kw = 0; kw < 3; ++kw) {
                    float wv = wp[kd * 9 + kh * 3 + kw];
                    a0 += trow[kw] * wv;
                    a1 += trow[kw + 8 * TILE_ROW] * wv;
                }
            }
        }
    }

    float bv = bias[0];
    size_t oi0 = (size_t)(b * 7 + d) * HW + (size_t)(ty + th) * 256 + tx + tw;
    size_t oi1 = oi0 + 8 * 256;
    float g0 = a0 + bv + x[oi0];
    float g1 = a1 + bv + x[oi1];
    g_guide[oi0] = g0; g_guide[oi1] = g1;
    out_prior[oi0] = g0; out_prior[oi1] = g1;
}

// ---------------- domain kernel: 4 blocks (one per bilateral block) ----------------
__global__ void domain_kernel(
    const float* __restrict__ spat,
    const float* __restrict__ dw1, const float* __restrict__ db1,
    const float* __restrict__ dw2, const float* __restrict__ db2)
{
    int i = blockIdx.x;
    int tid = threadIdx.x;
    __shared__ float sp[343], hid[1000], w1s[216], w2s[216];
    for (int t = tid; t < 343; t += 256) sp[t] = spat[t];
    for (int t = tid; t < 216; t += 256) { w1s[t] = dw1[i * 216 + t]; w2s[t] = dw2[i * 216 + t]; }
    __syncthreads();

    for (int idx = tid; idx < 1000; idx += 256) {
        int m = idx / 125, p = idx % 125;
        int z = p / 25, y = (p / 5) % 5, xx = p % 5;
        float a = db1[i * 8 + m];
#pragma unroll
        for (int kd = 0; kd < 3; ++kd)
#pragma unroll
            for (int kh = 0; kh < 3; ++kh)
#pragma unroll
                for (int kw = 0; kw < 3; ++kw)
                    a += sp[(z + kd) * 49 + (y + kh) * 7 + (xx + kw)] * w1s[m * 27 + kd * 9 + kh * 3 + kw];
        hid[idx] = fmaxf(a, 0.f);
    }
    __syncthreads();

    if (tid < 27) {
        int z = tid / 9, y = (tid / 3) % 3, xx = tid % 3;
        float a = db2[i];
#pragma unroll
        for (int m = 0; m < 8; ++m)
#pragma unroll
            for (int kd = 0; kd < 3; ++kd)
#pragma unroll
                for (int kh = 0; kh < 3; ++kh)
#pragma unroll
                    for (int kw = 0; kw < 3; ++kw)
                        a += hid[m * 125 + (z + kd) * 25 + (y + kh) * 5 + (xx + kw)] *
                             w2s[m * 27 + kd * 9 + kh * 3 + kw];
        g_domk[i * 27 + tid] = fmaxf(a, 0.f);
    }
}

// ---------------- range kernel v2: warp per pixel; normalized wt for 4 blocks ----
__global__ __launch_bounds__(256) void rangek_kernel(
    const float* __restrict__ rw1, const float* __restrict__ rb1,
    const float* __restrict__ rw2, const float* __restrict__ rb2)
{
    __shared__ float gp8[8][344];
    __shared__ float hid8[8][1008];
    __shared__ float w1s[216];      // relaid out [tap*8 + m]
    __shared__ float w2s[216];      // [m*27 + tap]

    int tid = threadIdx.x;
    int wid = tid >> 5, lane = tid & 31;
    int pix = blockIdx.x * 8 + wid;
    int b = pix >> 16;
    int hw = pix & 65535;
    int h = hw >> 8, wq = hw & 255;

    const float* gb = g_guide + (size_t)b * 7 * HW;
    float center = gb[3 * HW + hw];

    for (int idx = lane; idx < 343; idx += 32) {
        int d = idx / 49, rr = idx % 49;
        int ii = rr / 7, jj = rr % 7;
        int hh = h - 3 + ii, ww = wq - 3 + jj;
        float v = 0.f;
        if ((unsigned)hh < 256u && (unsigned)ww < 256u) v = gb[d * HW + hh * 256 + ww];
        gp8[wid][idx] = fabsf(v - center);
    }

    for (int i = 0; i < 4; ++i) {
        __syncthreads();
        for (int t = tid; t < 216; t += 256) {
            int m = t / 27, tap = t % 27;
            w1s[tap * 8 + m] = rw1[i * 216 + t];
            w2s[t] = rw2[i * 216 + t];
        }
        __syncthreads();

        const float* gp = gp8[wid];
        // layer 1: each lane computes 8 mid-channels for one 5x5x5 position
#pragma unroll
        for (int rep = 0; rep < 4; ++rep) {
            int p = lane + (rep << 5);
            int pp = p < 125 ? p : 124;
            int z = pp / 25, y = (pp / 5) % 5, xx = pp % 5;
            const float* gpb = gp + z * 49 + y * 7 + xx;
            float acc[8];
#pragma unroll
            for (int m = 0; m < 8; ++m) acc[m] = rb1[i * 8 + m];
#pragma unroll
            for (int kd = 0; kd < 3; ++kd)
#pragma unroll
                for (int kh = 0; kh < 3; ++kh)
#pragma unroll
                    for (int kw = 0; kw < 3; ++kw) {
                        float g = gpb[kd * 49 + kh * 7 + kw];
                        int tap = kd * 9 + kh * 3 + kw;
                        const float4* w4 = (const float4*)(w1s + tap * 8);
                        float4 wa = w4[0], wb = w4[1];
                        acc[0] += g * wa.x; acc[1] += g * wa.y;
                        acc[2] += g * wa.z; acc[3] += g * wa.w;
                        acc[4] += g * wb.x; acc[5] += g * wb.y;
                        acc[6] += g * wb.z; acc[7] += g * wb.w;
                    }
            if (p < 125) {
#pragma unroll
                for (int m = 0; m < 8; ++m)
                    hid8[wid][m * 125 + p] = fmaxf(acc[m], 0.f);
            }
        }
        __syncwarp();

        float wt = 0.f;
        if (lane < 27) {
            int z = lane / 9, y = (lane / 3) % 3, xx = lane % 3;
            float a = rb2[i];
            const float* hd = hid8[wid];
#pragma unroll
            for (int m = 0; m < 8; ++m)
#pragma unroll
                for (int kd = 0; kd < 3; ++kd)
#pragma unroll
                    for (int kh = 0; kh < 3; ++kh)
#pragma unroll
                        for (int kw = 0; kw < 3; ++kw)
                            a += hd[m * 125 + (z + kd) * 25 + (y + kh) * 5 + (xx + kw)] *
                                 w2s[m * 27 + kd * 9 + kh * 3 + kw];
            a = fmaxf(a, 0.f);
            wt = g_domk[i * 27 + lane] * a;
        }
        float s = wt;
#pragma unroll
        for (int off = 16; off; off >>= 1) s += __shfl_down_sync(0xffffffffu, s, off);
        s = __shfl_sync(0xffffffffu, s, 0);
        if (lane < 27)
            g_wt[((size_t)i * NPIX + pix) * 27 + lane] = wt / (s + 1e-6f);
        __syncwarp();
    }
}

// ---------------- bilateral gather per block i ----------------
__global__ void bilateral_kernel(int i, const float* __restrict__ x) {
    int pix = blockIdx.x * 256 + threadIdx.x;
    int b = pix >> 16;
    int hw = pix & 65535;
    int h = hw >> 8, wq = hw & 255;

    const float* wp = g_wt + ((size_t)i * NPIX + pix) * 27;
    const float* xcb = g_xc + (size_t)b * 3 * HW;

    float y = 0.f;
#pragma unroll
    for (int dz = 0; dz < 3; ++dz) {
#pragma unroll
        for (int dy = 0; dy < 3; ++dy) {
            int hh = h + dy - 1;
            bool hok = (unsigned)hh < 256u;
#pragma unroll
            for (int dx = 0; dx < 3; ++dx) {
                int ww = wq + dx - 1;
                bool wok = (unsigned)ww < 256u;
                float v = (hok && wok) ? xcb[dz * HW + hh * 256 + ww] : 0.f;
                y += wp[dz * 9 + dy * 3 + dx] * v;
            }
        }
    }
    y = fmaxf(y, 0.f);
    float ref = x[(b * 7 + 3) * HW + hw];
    g_ypre[pix] = y;
    g_r[pix] = y - ref;
}

// ---------------- alfa residual kernel per block i ----------------
__global__ void alfa_kernel(int i, const float* __restrict__ x,
                            const float* __restrict__ aw, const float* __restrict__ ab,
                            float* __restrict__ out)
{
    int pix = blockIdx.x * 256 + threadIdx.x;
    int b = pix >> 16;
    int hw = pix & 65535;
    int h = hw >> 8, wq = hw & 255;

    const float* awp = aw + i * 9;
    const float* rb = g_r + (size_t)b * HW;
    float alfa = ab[i];
#pragma unroll
    for (int ky = 0; ky < 3; ++ky) {
        int hh = h + ky - 1;
        if ((unsigned)hh >= 256u) continue;
#pragma unroll
        for (int kx = 0; kx < 3; ++kx) {
            int ww = wq + kx - 1;
            if ((unsigned)ww >= 256u) continue;
            alfa += awp[ky * 3 + kx] * rb[hh * 256 + ww];
        }
    }
    float rc = g_r[pix];
    float y = fmaxf(g_ypre[pix] + alfa * rc, 0.f);

    out[OUT_Y + (size_t)i * NPIX + pix] = y;
    g_xc[(b * 3 + 1) * HW + hw] = y;
    if (i == 0) {
        g_xc[(b * 3 + 0) * HW + hw] = fmaxf(x[(b * 7 + 2) * HW + hw], 0.f);
        g_xc[(b * 3 + 2) * HW + hw] = fmaxf(x[(b * 7 + 4) * HW + hw], 0.f);
    }
    if (i == 3) {
        out[(b * 3 + 0) * HW + hw] = g_xc[(b * 3 + 0) * HW + hw];
        out[(b * 3 + 1) * HW + hw] = y;
        out[(b * 3 + 2) * HW + hw] = g_xc[(b * 3 + 2) * HW + hw];
    }
}

// ---------------- launch ----------------
extern "C" void kernel_launch(void* const* d_in, const int* in_sizes, int n_in,
                              void* d_out, int out_size)
{
    const float* x    = (const float*)d_in[0];
    const float* spat = (const float*)d_in[1];
    const float* pw1  = (const float*)d_in[2];
    const float* pb1  = (const float*)d_in[3];
    const float* pw2  = (const float*)d_in[4];
    const float* pb2  = (const float*)d_in[5];
    const float* pw3  = (const float*)d_in[6];
    const float* pb3  = (const float*)d_in[7];
    const float* pw4  = (const float*)d_in[8];
    const float* pb4  = (const float*)d_in[9];
    const float* dw1  = (const float*)d_in[10];
    const float* db1  = (const float*)d_in[11];
    const float* dw2  = (const float*)d_in[12];
    const float* db2  = (const float*)d_in[13];
    const float* rw1  = (const float*)d_in[14];
    const float* rb1  = (const float*)d_in[15];
    const float* rw2  = (const float*)d_in[16];
    const float* rb2  = (const float*)d_in[17];
    const float* aw   = (const float*)d_in[18];
    const float* ab   = (const float*)d_in[19];
    float* out = (float*)d_out;

    cudaFuncSetAttribute(conv32_v6, cudaFuncAttributeMaxDynamicSharedMemorySize, CONV6SM);

    init_xc_kernel<<<1536, 256>>>(x);
    conv1_kernel<<<dim3(256, 7, 2), 256>>>(x, pw1, pb1);
    conv32_v6<<<dim3(64, 7, 8), 256, CONV6SM>>>(0, pw2, pb2);   // h1 -> h2
    conv32_v6<<<dim3(64, 7, 8), 256, CONV6SM>>>(1, pw3, pb3);   // h2 -> h1
    conv4_v2<<<dim3(128, 7, 2), 256>>>(x, pw4, pb4, out + OUT_PRIOR);
    domain_kernel<<<4, 256>>>(spat, dw1, db1, dw2, db2);
    rangek_kernel<<<NPIX / 8, 256>>>(rw1, rb1, rw2, rb2);

    for (int i = 0; i < 4; ++i) {
        bilateral_kernel<<<NPIX / 256, 256>>>(i, x);
        alfa_kernel<<<NPIX / 256, 256>>>(i, x, aw, ab, out);
    }
}

// round 9
// speedup vs baseline: 1.5991x; 1.3118x over previous
#include <cuda_runtime.h>
#include <cstdint>

#define HW 65536
#define NPIX 131072   // B * H * W = 2*256*256
#define OUT_PRIOR 393216
#define OUT_Y 1310720

typedef unsigned long long ull;

__device__ __forceinline__ ull pack2(float lo, float hi) {
    ull r; asm("mov.b64 %0, {%1, %2};" : "=l"(r) : "f"(lo), "f"(hi)); return r;
}
__device__ __forceinline__ void unpack2(ull v, float& lo, float& hi) {
    asm("mov.b64 {%0, %1}, %2;" : "=f"(lo), "=f"(hi) : "l"(v));
}
__device__ __forceinline__ void ffma2(ull& d, ull a, ull b) {
    asm("fma.rn.f32x2 %0, %1, %2, %0;" : "+l"(d) : "l"(a), "l"(b));
}
__device__ __forceinline__ ull addf2(ull a, ull b) {
    ull r; asm("add.rn.f32x2 %0, %1, %2;" : "=l"(r) : "l"(a), "l"(b)); return r;
}

// ---------------- device scratch (static: no allocs allowed) ----------------
__device__ float g_h1[2u*32u*7u*HW];
__device__ float g_h2[2u*32u*7u*HW];
__device__ float g_guide[2u*7u*HW];
__device__ float g_domk[4*27];
__device__ float g_wt[4u*NPIX*27u];
__device__ float g_xc[2u*3u*HW];
__device__ float g_ypre[NPIX];
__device__ float g_r[NPIX];

// ---------------- init: xc = x[:, :, 2:5] (raw, no relu) ----------------
__global__ void init_xc_kernel(const float* __restrict__ x) {
    int t = blockIdx.x * 256 + threadIdx.x;           // 0 .. 393215
    int b = t / (3 * HW);
    int rem = t - b * 3 * HW;
    int s = rem / HW;
    int hw = rem - s * HW;
    g_xc[t] = x[(b * 7 + 2 + s) * HW + hw];
}

// ---------------- conv1: 1 -> 32, 3x3x3 SAME, relu ----------------
__global__ __launch_bounds__(256) void conv1_kernel(
    const float* __restrict__ x, const float* __restrict__ w, const float* __restrict__ bias)
{
    __shared__ float ws[27 * 32];   // [tap][oc]
    __shared__ float bs[32];
    int tid = threadIdx.x;
    for (int t = tid; t < 864; t += 256) {
        int tap = t >> 5, oc = t & 31;
        ws[t] = w[oc * 27 + tap];
    }
    if (tid < 32) bs[tid] = bias[tid];
    __syncthreads();

    int hw = blockIdx.x * 256 + tid;
    int h = hw >> 8, wq = hw & 255;
    int d = blockIdx.y, b = blockIdx.z;

    const float* xp = x + (size_t)(b * 7 + d) * HW + hw;
    bool h0 = h > 0, h2 = h < 255, w0 = wq > 0, w2 = wq < 255;

    float v[27];
#pragma unroll
    for (int kd = 0; kd < 3; ++kd) {
        int dd = d + kd - 1;
        bool dok = (unsigned)dd < 7u;
        const float* ipd = xp + (kd - 1) * HW;
#pragma unroll
        for (int kh = 0; kh < 3; ++kh) {
            bool hok = (kh == 0) ? h0 : (kh == 2 ? h2 : true);
            const float* iph = ipd + (kh - 1) * 256;
#pragma unroll
            for (int kw = 0; kw < 3; ++kw) {
                bool wok = (kw == 0) ? w0 : (kw == 2 ? w2 : true);
                v[kd * 9 + kh * 3 + kw] = (dok && hok && wok) ? iph[kw - 1] : 0.f;
            }
        }
    }

    float acc[32];
#pragma unroll
    for (int oc = 0; oc < 32; ++oc) acc[oc] = bs[oc];

    const float4* wp = (const float4*)ws;
#pragma unroll
    for (int tap = 0; tap < 27; ++tap) {
        float xv = v[tap];
#pragma unroll
        for (int q = 0; q < 8; ++q) {
            float4 ww = wp[tap * 8 + q];
            acc[q * 4 + 0] += xv * ww.x;
            acc[q * 4 + 1] += xv * ww.y;
            acc[q * 4 + 2] += xv * ww.z;
            acc[q * 4 + 3] += xv * ww.w;
        }
    }

    float* ob = g_h1 + (size_t)b * 32 * 7 * HW + (size_t)d * HW + hw;
#pragma unroll
    for (int oc = 0; oc < 32; ++oc)
        ob[(size_t)oc * 7 * HW] = fmaxf(acc[oc], 0.f);
}

// ---------------- conv32 v4 (proven): f32x2, 8 oc/block, 4 px/thread, 16x64 tile ----
#define T4ROW 66
#define T4SLICE 1188           // 18*66
#define T4ELEMS 3564           // 3*18*66
#define CONV4SM (27648 + 64 + 2 * T4ELEMS * 4)   // 56,224 B
__global__ __launch_bounds__(256, 2) void conv32_v4(
    int dir, const float* __restrict__ w, const float* __restrict__ bias)
{
    extern __shared__ char smemraw[];
    float* wsm = (float*)smemraw;               // 6912 floats [(ic*27+tap)*8 + o]
    ull*   bs2 = (ull*)(smemraw + 27648);       // 8 ull
    float* tls = (float*)(smemraw + 27712);     // 2 * 3564 floats

    int tid = threadIdx.x;
    int zb = blockIdx.z;
    int b = zb >> 2, ocg = zb & 3;

    for (int t = tid; t < 6912; t += 256) {
        int o = t & 7;
        int rest = t >> 3;                      // = ic*27 + tap
        int ic = rest / 27, tap = rest - ic * 27;
        wsm[t] = w[((ocg * 8 + o) * 32 + ic) * 27 + tap];
    }
    if (tid < 8) { float bv = bias[ocg * 8 + tid]; bs2[tid] = pack2(bv, bv); }

    int tile = blockIdx.x;                      // 0..63
    int tx = (tile & 3) << 6;                   // w origin (0,64,128,192)
    int ty = (tile >> 2) << 4;                  // h origin (0..240)
    int d = blockIdx.y;
    int tw = tid & 31, th = tid >> 5;

    const float* in = dir ? g_h2 : g_h1;
    float* out = dir ? g_h1 : g_h2;
    const float* inb = in + (size_t)b * 32 * 7 * HW;

    // preload ic = 0 into buffer 0
    {
        const float* ip = inb;
#pragma unroll
        for (int k = 0; k < 14; ++k) {
            int idx = tid + (k << 8);
            if (idx < T4ELEMS) {
                int dd = (idx >= T4SLICE) + (idx >= 2 * T4SLICE);
                int r  = idx - dd * T4SLICE;
                int hh = r / T4ROW;
                int ww = r - hh * T4ROW;
                int gd = d + dd - 1, gh = ty + hh - 1, gw = tx + ww - 1;
                float v = 0.f;
                if ((unsigned)gd < 7u && (unsigned)gh < 256u && (unsigned)gw < 256u)
                    v = ip[(size_t)gd * HW + gh * 256 + gw];
                tls[idx] = v;
            }
        }
    }

    ull a[16];   // a[o] col-group 0, a[8+o] col-group 1
#pragma unroll
    for (int o = 0; o < 16; ++o) a[o] = 0ull;

    __syncthreads();   // weights + first tile ready

    for (int ic = 0; ic < 32; ++ic) {
        const float* cur = tls + (ic & 1) * T4ELEMS;

        // stage next input tile in registers (hidden behind compute)
        float stage[14];
        if (ic < 31) {
            const float* ip = inb + (size_t)(ic + 1) * 7 * HW;
#pragma unroll
            for (int k = 0; k < 14; ++k) {
                int idx = tid + (k << 8);
                float v = 0.f;
                if (idx < T4ELEMS) {
                    int dd = (idx >= T4SLICE) + (idx >= 2 * T4SLICE);
                    int r  = idx - dd * T4SLICE;
                    int hh = r / T4ROW;
                    int ww = r - hh * T4ROW;
                    int gd = d + dd - 1, gh = ty + hh - 1, gw = tx + ww - 1;
                    if ((unsigned)gd < 7u && (unsigned)gh < 256u && (unsigned)gw < 256u)
                        v = ip[(size_t)gd * HW + gh * 256 + gw];
                }
                stage[k] = v;
            }
        }

        const float* wp = wsm + ic * 216;     // 27 taps * 8 oc
#pragma unroll
        for (int kd = 0; kd < 3; ++kd) {
#pragma unroll
            for (int kh = 0; kh < 3; ++kh) {
                const float* r0 = cur + kd * T4SLICE + (th + kh) * T4ROW + tw;
                const float* r1 = r0 + 8 * T4ROW;
#pragma unroll
                for (int kw = 0; kw < 3; ++kw) {
                    ull p0 = pack2(r0[kw],      r1[kw]);
                    ull p1 = pack2(r0[kw + 32], r1[kw + 32]);
                    const float4* w4 = (const float4*)(wp + ((kd * 9 + kh * 3 + kw) << 3));
                    float4 wa = w4[0], wb = w4[1];
                    ull w0 = pack2(wa.x, wa.x), w1 = pack2(wa.y, wa.y);
                    ull w2 = pack2(wa.z, wa.z), w3 = pack2(wa.w, wa.w);
                    ull w4u = pack2(wb.x, wb.x), w5 = pack2(wb.y, wb.y);
                    ull w6 = pack2(wb.z, wb.z), w7 = pack2(wb.w, wb.w);
                    ffma2(a[0], p0, w0);  ffma2(a[8],  p1, w0);
                    ffma2(a[1], p0, w1);  ffma2(a[9],  p1, w1);
                    ffma2(a[2], p0, w2);  ffma2(a[10], p1, w2);
                    ffma2(a[3], p0, w3);  ffma2(a[11], p1, w3);
                    ffma2(a[4], p0, w4u); ffma2(a[12], p1, w4u);
                    ffma2(a[5], p0, w5);  ffma2(a[13], p1, w5);
                    ffma2(a[6], p0, w6);  ffma2(a[14], p1, w6);
                    ffma2(a[7], p0, w7);  ffma2(a[15], p1, w7);
                }
            }
        }

        if (ic < 31) {
            float* nxt = tls + ((ic + 1) & 1) * T4ELEMS;
#pragma unroll
            for (int k = 0; k < 14; ++k) {
                int idx = tid + (k << 8);
                if (idx < T4ELEMS) nxt[idx] = stage[k];
            }
            __syncthreads();
        }
    }

    size_t ob = (size_t)b * 32 * 7 * HW + (size_t)d * HW + (size_t)(ty + th) * 256 + tx + tw;
#pragma unroll
    for (int o = 0; o < 8; ++o) {
        size_t pp = ob + (size_t)(ocg * 8 + o) * 7 * HW;
        float lo, hi;
        unpack2(addf2(a[o], bs2[o]), lo, hi);
        out[pp] = fmaxf(lo, 0.f);
        out[pp + 8 * 256] = fmaxf(hi, 0.f);
        unpack2(addf2(a[8 + o], bs2[o]), lo, hi);
        out[pp + 32] = fmaxf(lo, 0.f);
        out[pp + 8 * 256 + 32] = fmaxf(hi, 0.f);
    }
}

// ---------------- conv4 v4: 32 -> 1 SAME + x, double-buffered pipeline ----
#define TILE_ROW 34
#define TILE_SLICE 612
#define TILE_ELEMS 1836
__global__ __launch_bounds__(256) void conv4_v4(
    const float* __restrict__ x, const float* __restrict__ w,
    const float* __restrict__ bias, float* __restrict__ out_prior)
{
    __shared__ float ws[864];               // [ic*27+tap]
    __shared__ float tls[2 * TILE_ELEMS];
    int tid = threadIdx.x;
    for (int t = tid; t < 864; t += 256) ws[t] = w[t];

    int tileId = blockIdx.x;
    int tx = (tileId & 7) << 5;
    int ty = (tileId >> 3) << 4;
    int d = blockIdx.y, b = blockIdx.z;
    int tw = tid & 31, th = tid >> 5;

    const float* inb = g_h1 + (size_t)b * 32 * 7 * HW;

    // preload ic = 0
    {
        const float* ip = inb;
#pragma unroll
        for (int k = 0; k < 8; ++k) {
            int idx = tid + (k << 8);
            if (idx < TILE_ELEMS) {
                int dd = idx / TILE_SLICE;
                int r  = idx - dd * TILE_SLICE;
                int hh = r / TILE_ROW;
                int ww = r - hh * TILE_ROW;
                int gd = d + dd - 1, gh = ty + hh - 1, gw = tx + ww - 1;
                float v = 0.f;
                if ((unsigned)gd < 7u && (unsigned)gh < 256u && (unsigned)gw < 256u)
                    v = ip[(size_t)gd * HW + gh * 256 + gw];
                tls[idx] = v;
            }
        }
    }

    float a0 = 0.f, a1 = 0.f;
    __syncthreads();

    for (int ic = 0; ic < 32; ++ic) {
        const float* cur = tls + (ic & 1) * TILE_ELEMS;

        float stage[8];
        if (ic < 31) {
            const float* ip = inb + (size_t)(ic + 1) * 7 * HW;
#pragma unroll
            for (int k = 0; k < 8; ++k) {
                int idx = tid + (k << 8);
                float v = 0.f;
                if (idx < TILE_ELEMS) {
                    int dd = idx / TILE_SLICE;
                    int r  = idx - dd * TILE_SLICE;
                    int hh = r / TILE_ROW;
                    int ww = r - hh * TILE_ROW;
                    int gd = d + dd - 1, gh = ty + hh - 1, gw = tx + ww - 1;
                    if ((unsigned)gd < 7u && (unsigned)gh < 256u && (unsigned)gw < 256u)
                        v = ip[(size_t)gd * HW + gh * 256 + gw];
                }
                stage[k] = v;
            }
        }

        const float* wp = ws + ic * 27;
#pragma unroll
        for (int kd = 0; kd < 3; ++kd) {
#pragma unroll
            for (int kh = 0; kh < 3; ++kh) {
                const float* trow = cur + kd * TILE_SLICE + (th + kh) * TILE_ROW + tw;
#pragma unroll
                for (int kw = 0; kw < 3; ++kw) {
                    float wv = wp[kd * 9 + kh * 3 + kw];
                    a0 += trow[kw] * wv;
                    a1 += trow[kw + 8 * TILE_ROW] * wv;
                }
            }
        }

        if (ic < 31) {
            float* nxt = tls + ((ic + 1) & 1) * TILE_ELEMS;
#pragma unroll
            for (int k = 0; k < 8; ++k) {
                int idx = tid + (k << 8);
                if (idx < TILE_ELEMS) nxt[idx] = stage[k];
            }
            __syncthreads();
        }
    }

    float bv = bias[0];
    size_t oi0 = (size_t)(b * 7 + d) * HW + (size_t)(ty + th) * 256 + tx + tw;
    size_t oi1 = oi0 + 8 * 256;
    float g0 = a0 + bv + x[oi0];
    float g1 = a1 + bv + x[oi1];
    g_guide[oi0] = g0; g_guide[oi1] = g1;
    out_prior[oi0] = g0; out_prior[oi1] = g1;
}

// ---------------- domain kernel: 4 blocks (one per bilateral block) ----------------
__global__ void domain_kernel(
    const float* __restrict__ spat,
    const float* __restrict__ dw1, const float* __restrict__ db1,
    const float* __restrict__ dw2, const float* __restrict__ db2)
{
    int i = blockIdx.x;
    int tid = threadIdx.x;
    __shared__ float sp[343], hid[1000], w1s[216], w2s[216];
    for (int t = tid; t < 343; t += 256) sp[t] = spat[t];
    for (int t = tid; t < 216; t += 256) { w1s[t] = dw1[i * 216 + t]; w2s[t] = dw2[i * 216 + t]; }
    __syncthreads();

    for (int idx = tid; idx < 1000; idx += 256) {
        int m = idx / 125, p = idx % 125;
        int z = p / 25, y = (p / 5) % 5, xx = p % 5;
        float a = db1[i * 8 + m];
#pragma unroll
        for (int kd = 0; kd < 3; ++kd)
#pragma unroll
            for (int kh = 0; kh < 3; ++kh)
#pragma unroll
                for (int kw = 0; kw < 3; ++kw)
                    a += sp[(z + kd) * 49 + (y + kh) * 7 + (xx + kw)] * w1s[m * 27 + kd * 9 + kh * 3 + kw];
        hid[idx] = fmaxf(a, 0.f);
    }
    __syncthreads();

    if (tid < 27) {
        int z = tid / 9, y = (tid / 3) % 3, xx = tid % 3;
        float a = db2[i];
#pragma unroll
        for (int m = 0; m < 8; ++m)
#pragma unroll
            for (int kd = 0; kd < 3; ++kd)
#pragma unroll
                for (int kh = 0; kh < 3; ++kh)
#pragma unroll
                    for (int kw = 0; kw < 3; ++kw)
                        a += hid[m * 125 + (z + kd) * 25 + (y + kh) * 5 + (xx + kw)] *
                             w2s[m * 27 + kd * 9 + kh * 3 + kw];
        g_domk[i * 27 + tid] = fmaxf(a, 0.f);
    }
}

// ---------------- range kernel v3: warp/pixel, tap-outer layer1 ----
__global__ __launch_bounds__(256) void rangek_kernel(
    const float* __restrict__ rw1, const float* __restrict__ rb1,
    const float* __restrict__ rw2, const float* __restrict__ rb2)
{
    __shared__ float gp8[8][344];
    __shared__ float hid8[8][1008];
    __shared__ float w1s[216];      // [tap*8 + m]
    __shared__ float w2s[216];      // [m*27 + tap]

    int tid = threadIdx.x;
    int wid = tid >> 5, lane = tid & 31;
    int pix = blockIdx.x * 8 + wid;
    int b = pix >> 16;
    int hw = pix & 65535;
    int h = hw >> 8, wq = hw & 255;

    const float* gb = g_guide + (size_t)b * 7 * HW;
    float center = gb[3 * HW + hw];

    for (int idx = lane; idx < 343; idx += 32) {
        int d = idx / 49, rr = idx % 49;
        int ii = rr / 7, jj = rr % 7;
        int hh = h - 3 + ii, ww = wq - 3 + jj;
        float v = 0.f;
        if ((unsigned)hh < 256u && (unsigned)ww < 256u) v = gb[d * HW + hh * 256 + ww];
        gp8[wid][idx] = fabsf(v - center);
    }

    // per-rep position offsets (fixed across i)
    int off[4];
#pragma unroll
    for (int rep = 0; rep < 4; ++rep) {
        int p = lane + (rep << 5);
        int pp = p < 125 ? p : 124;
        int z = pp / 25, y = (pp / 5) % 5, xx = pp % 5;
        off[rep] = z * 49 + y * 7 + xx;
    }

    for (int i = 0; i < 4; ++i) {
        __syncthreads();
        for (int t = tid; t < 216; t += 256) {
            int m = t / 27, tap = t % 27;
            w1s[tap * 8 + m] = rw1[i * 216 + t];
            w2s[t] = rw2[i * 216 + t];
        }
        __syncthreads();

        const float* gp = gp8[wid];
        float acc[32];   // [rep][m]
#pragma unroll
        for (int m = 0; m < 8; ++m) {
            float bv = rb1[i * 8 + m];
            acc[m] = bv; acc[8 + m] = bv; acc[16 + m] = bv; acc[24 + m] = bv;
        }

#pragma unroll
        for (int kd = 0; kd < 3; ++kd)
#pragma unroll
            for (int kh = 0; kh < 3; ++kh)
#pragma unroll
                for (int kw = 0; kw < 3; ++kw) {
                    int tap = kd * 9 + kh * 3 + kw;
                    const float4* w4 = (const float4*)(w1s + tap * 8);
                    float4 wa = w4[0], wb = w4[1];
                    int to = kd * 49 + kh * 7 + kw;
#pragma unroll
                    for (int rep = 0; rep < 4; ++rep) {
                        float g = gp[off[rep] + to];
                        float* ac = acc + rep * 8;
                        ac[0] += g * wa.x; ac[1] += g * wa.y;
                        ac[2] += g * wa.z; ac[3] += g * wa.w;
                        ac[4] += g * wb.x; ac[5] += g * wb.y;
                        ac[6] += g * wb.z; ac[7] += g * wb.w;
                    }
                }

#pragma unroll
        for (int rep = 0; rep < 4; ++rep) {
            int p = lane + (rep << 5);
            if (p < 125) {
#pragma unroll
                for (int m = 0; m < 8; ++m)
                    hid8[wid][m * 125 + p] = fmaxf(acc[rep * 8 + m], 0.f);
            }
        }
        __syncwarp();

        float wt = 0.f;
        if (lane < 27) {
            int z = lane / 9, y = (lane / 3) % 3, xx = lane % 3;
            float a = rb2[i];
            const float* hd = hid8[wid];
#pragma unroll
            for (int m = 0; m < 8; ++m)
#pragma unroll
                for (int kd = 0; kd < 3; ++kd)
#pragma unroll
                    for (int kh = 0; kh < 3; ++kh)
#pragma unroll
                        for (int kw = 0; kw < 3; ++kw)
                            a += hd[m * 125 + (z + kd) * 25 + (y + kh) * 5 + (xx + kw)] *
                                 w2s[m * 27 + kd * 9 + kh * 3 + kw];
            a = fmaxf(a, 0.f);
            wt = g_domk[i * 27 + lane] * a;
        }
        float s = wt;
#pragma unroll
        for (int off2 = 16; off2; off2 >>= 1) s += __shfl_down_sync(0xffffffffu, s, off2);
        s = __shfl_sync(0xffffffffu, s, 0);
        if (lane < 27)
            g_wt[((size_t)i * NPIX + pix) * 27 + lane] = wt / (s + 1e-6f);
        __syncwarp();
    }
}

// ---------------- bilateral gather per block i ----------------
__global__ void bilateral_kernel(int i, const float* __restrict__ x) {
    int pix = blockIdx.x * 256 + threadIdx.x;
    int b = pix >> 16;
    int hw = pix & 65535;
    int h = hw >> 8, wq = hw & 255;

    const float* wp = g_wt + ((size_t)i * NPIX + pix) * 27;
    const float* xcb = g_xc + (size_t)b * 3 * HW;

    float y = 0.f;
#pragma unroll
    for (int dz = 0; dz < 3; ++dz) {
#pragma unroll
        for (int dy = 0; dy < 3; ++dy) {
            int hh = h + dy - 1;
            bool hok = (unsigned)hh < 256u;
#pragma unroll
            for (int dx = 0; dx < 3; ++dx) {
                int ww = wq + dx - 1;
                bool wok = (unsigned)ww < 256u;
                float v = (hok && wok) ? xcb[dz * HW + hh * 256 + ww] : 0.f;
                y += wp[dz * 9 + dy * 3 + dx] * v;
            }
        }
    }
    y = fmaxf(y, 0.f);
    float ref = x[(b * 7 + 3) * HW + hw];
    g_ypre[pix] = y;
    g_r[pix] = y - ref;
}

// ---------------- alfa residual kernel per block i ----------------
__global__ void alfa_kernel(int i, const float* __restrict__ x,
                            const float* __restrict__ aw, const float* __restrict__ ab,
                            float* __restrict__ out)
{
    int pix = blockIdx.x * 256 + threadIdx.x;
    int b = pix >> 16;
    int hw = pix & 65535;
    int h = hw >> 8, wq = hw & 255;

    const float* awp = aw + i * 9;
    const float* rb = g_r + (size_t)b * HW;
    float alfa = ab[i];
#pragma unroll
    for (int ky = 0; ky < 3; ++ky) {
        int hh = h + ky - 1;
        if ((unsigned)hh >= 256u) continue;
#pragma unroll
        for (int kx = 0; kx < 3; ++kx) {
            int ww = wq + kx - 1;
            if ((unsigned)ww >= 256u) continue;
            alfa += awp[ky * 3 + kx] * rb[hh * 256 + ww];
        }
    }
    float rc = g_r[pix];
    float y = fmaxf(g_ypre[pix] + alfa * rc, 0.f);

    out[OUT_Y + (size_t)i * NPIX + pix] = y;
    g_xc[(b * 3 + 1) * HW + hw] = y;
    if (i == 0) {
        g_xc[(b * 3 + 0) * HW + hw] = fmaxf(x[(b * 7 + 2) * HW + hw], 0.f);
        g_xc[(b * 3 + 2) * HW + hw] = fmaxf(x[(b * 7 + 4) * HW + hw], 0.f);
    }
    if (i == 3) {
        out[(b * 3 + 0) * HW + hw] = g_xc[(b * 3 + 0) * HW + hw];
        out[(b * 3 + 1) * HW + hw] = y;
        out[(b * 3 + 2) * HW + hw] = g_xc[(b * 3 + 2) * HW + hw];
    }
}

// ---------------- launch ----------------
extern "C" void kernel_launch(void* const* d_in, const int* in_sizes, int n_in,
                              void* d_out, int out_size)
{
    const float* x    = (const float*)d_in[0];
    const float* spat = (const float*)d_in[1];
    const float* pw1  = (const float*)d_in[2];
    const float* pb1  = (const float*)d_in[3];
    const float* pw2  = (const float*)d_in[4];
    const float* pb2  = (const float*)d_in[5];
    const float* pw3  = (const float*)d_in[6];
    const float* pb3  = (const float*)d_in[7];
    const float* pw4  = (const float*)d_in[8];
    const float* pb4  = (const float*)d_in[9];
    const float* dw1  = (const float*)d_in[10];
    const float* db1  = (const float*)d_in[11];
    const float* dw2  = (const float*)d_in[12];
    const float* db2  = (const float*)d_in[13];
    const float* rw1  = (const float*)d_in[14];
    const float* rb1  = (const float*)d_in[15];
    const float* rw2  = (const float*)d_in[16];
    const float* rb2  = (const float*)d_in[17];
    const float* aw   = (const float*)d_in[18];
    const float* ab   = (const float*)d_in[19];
    float* out = (float*)d_out;

    cudaFuncSetAttribute(conv32_v4, cudaFuncAttributeMaxDynamicSharedMemorySize, CONV4SM);

    init_xc_kernel<<<1536, 256>>>(x);
    conv1_kernel<<<dim3(256, 7, 2), 256>>>(x, pw1, pb1);
    conv32_v4<<<dim3(64, 7, 8), 256, CONV4SM>>>(0, pw2, pb2);   // h1 -> h2
    conv32_v4<<<dim3(64, 7, 8), 256, CONV4SM>>>(1, pw3, pb3);   // h2 -> h1
    conv4_v4<<<dim3(128, 7, 2), 256>>>(x, pw4, pb4, out + OUT_PRIOR);
    domain_kernel<<<4, 256>>>(spat, dw1, db1, dw2, db2);
    rangek_kernel<<<NPIX / 8, 256>>>(rw1, rb1, rw2, rb2);

    for (int i = 0; i < 4; ++i) {
        bilateral_kernel<<<NPIX / 256, 256>>>(i, x);
        alfa_kernel<<<NPIX / 256, 256>>>(i, x, aw, ab, out);
    }
}